// round 12
// baseline (speedup 1.0000x reference)
#include <cuda_runtime.h>
#include <cuda_fp16.h>
#include <math.h>
#include <stdint.h>

#define N_HEAD   16
#define HEAD_DIM 64
#define EMBD     1024
#define BATCH    2
#define SEQ      2048
#define M_TOTAL  (BATCH*SEQ)   // 4096

// Q is pre-scaled by 1/sqrt(64) * log2(e) so flash softmax runs in log2 domain.
#define QSC 0.1803368801111204f

// ---------------- scratch (device globals; no allocs allowed) ---------------
__device__ __half g_qh[(size_t)BATCH*N_HEAD*SEQ*HEAD_DIM];   // Q fp16 (pre-scaled)
__device__ __half g_kh[(size_t)BATCH*N_HEAD*SEQ*HEAD_DIM];   // K fp16 copy
__device__ __half g_vh[(size_t)BATCH*N_HEAD*SEQ*HEAD_DIM];   // V fp16 copy
__device__ __half g_ah[(size_t)M_TOTAL*EMBD];                // attn out fp16 [B*S,E]
__device__ __half g_xh[(size_t)M_TOTAL*EMBD];                // x fp16
__device__ __half g_wqkvh[(size_t)3*EMBD*EMBD];              // W_qkv^T fp16 [3072,1024]
__device__ __half g_wprojh[(size_t)EMBD*EMBD];               // W_proj^T fp16 [1024,1024]

// ---------------- helpers ---------------------------------------------------
__device__ __forceinline__ uint32_t smem_u32(const void* p) {
    uint32_t a;
    asm("{ .reg .u64 t; cvta.to.shared.u64 t, %1; cvt.u32.u64 %0, t; }" : "=r"(a) : "l"(p));
    return a;
}
__device__ __forceinline__ uint32_t packh2(float x, float y) {
    __half2 h = __floats2half2_rn(x, y);
    return *(uint32_t*)&h;
}
__device__ __forceinline__ float ex2f(float x) {
    float y;
    asm("ex2.approx.f32 %0, %1;" : "=f"(y) : "f"(x));
    return y;
}
__device__ __forceinline__ void mma_f16(float* c, const uint32_t* a, const uint32_t* b) {
    asm volatile("mma.sync.aligned.m16n8k16.row.col.f32.f16.f16.f32 "
        "{%0,%1,%2,%3}, {%4,%5,%6,%7}, {%8,%9}, {%0,%1,%2,%3};"
        : "+f"(c[0]), "+f"(c[1]), "+f"(c[2]), "+f"(c[3])
        : "r"(a[0]), "r"(a[1]), "r"(a[2]), "r"(a[3]), "r"(b[0]), "r"(b[1]));
}
__device__ __forceinline__ void ldm_x4(uint32_t* r, uint32_t addr) {
    asm volatile("ldmatrix.sync.aligned.m8n8.x4.shared.b16 {%0,%1,%2,%3}, [%4];"
        : "=r"(r[0]), "=r"(r[1]), "=r"(r[2]), "=r"(r[3]) : "r"(addr));
}
__device__ __forceinline__ void ldm_x4_t(uint32_t* r, uint32_t addr) {
    asm volatile("ldmatrix.sync.aligned.m8n8.x4.trans.shared.b16 {%0,%1,%2,%3}, [%4];"
        : "=r"(r[0]), "=r"(r[1]), "=r"(r[2]), "=r"(r[3]) : "r"(addr));
}
__device__ __forceinline__ void cp16(void* dst_smem, const void* src) {
    uint32_t d = smem_u32(dst_smem);
    asm volatile("cp.async.cg.shared.global [%0], [%1], 16;" :: "r"(d), "l"(src) : "memory");
}
#define CP_COMMIT() asm volatile("cp.async.commit_group;" ::: "memory")
#define CP_WAIT(n)  asm volatile("cp.async.wait_group %0;" :: "n"(n) : "memory")

// ---------------- prep kernels ----------------------------------------------
__global__ __launch_bounds__(256)
void to_half_kernel(const float* __restrict__ x, __half* __restrict__ y, int n8)
{
    int i = blockIdx.x * blockDim.x + threadIdx.x;
    if (i < n8) {
        float4 a = ((const float4*)x)[2 * i];
        float4 b = ((const float4*)x)[2 * i + 1];
        uint4 o;
        o.x = packh2(a.x, a.y); o.y = packh2(a.z, a.w);
        o.z = packh2(b.x, b.y); o.w = packh2(b.z, b.w);
        ((uint4*)y)[i] = o;
    }
}

// Merged transpose of both weight matrices: blocks 0..95 -> qkv, 96..127 -> proj
__global__ __launch_bounds__(256)
void transpose_both_kernel(const float* __restrict__ Wq, const float* __restrict__ Wp,
                           __half* __restrict__ WTq, __half* __restrict__ WTp)
{
    __shared__ float t[32][33];
    bool is_q = blockIdx.x < 96;
    const float* W  = is_q ? Wq  : Wp;
    __half* WT      = is_q ? WTq : WTp;
    int N           = is_q ? 3 * EMBD : EMBD;
    int n0 = (is_q ? blockIdx.x : blockIdx.x - 96) * 32;
    int k0 = blockIdx.y * 32;
    int tx = threadIdx.x, ty = threadIdx.y;
#pragma unroll
    for (int i = 0; i < 4; i++)
        t[ty + 8 * i][tx] = W[(size_t)(k0 + ty + 8 * i) * N + n0 + tx];
    __syncthreads();
#pragma unroll
    for (int i = 0; i < 4; i++)
        WT[(size_t)(n0 + ty + 8 * i) * EMBD + k0 + tx] = __float2half(t[tx][ty + 8 * i]);
}

// ---------------- fp16 mma.sync GEMM ----------------------------------------
// C[M,Ntot] = A[M,1024] @ Bt^T + bias.  Block 128x128, BK=64, 3-stage cp.async,
// one barrier per K-tile, A-fragments register double-buffered across k16 steps.
// Odd warps traverse the 4 k16 steps in REVERSE order to stagger LDSM/MMA
// bursts across warps (accumulation order per warp is commutative).
#define GSH 72       // stride (halves) = 144B: 64 data + 8 pad; ldmatrix conflict-free
#define GKT (EMBD/64)

__global__ __launch_bounds__(256, 2)
void gemm_tc(const __half* __restrict__ A, const __half* __restrict__ Bt,
             const float* __restrict__ bias, int mode,
             float* __restrict__ o0, float* __restrict__ o1, float* __restrict__ o2,
             __half* __restrict__ h0, __half* __restrict__ h1, __half* __restrict__ h2)
{
    extern __shared__ __half smg[];
    __half* SA = smg;                      // [3][128*GSH]
    __half* SB = smg + 3 * 128 * GSH;      // [3][128*GSH]

    const int tid = threadIdx.x, wid = tid >> 5, lane = tid & 31;
    const int g = lane >> 2, t4 = lane & 3;
    const int wm = wid >> 1, wn = wid & 1;
    const int rev = wid & 1;               // odd warps run k16 steps 3..0
    const int m0 = blockIdx.y * 128, n0 = blockIdx.x * 128;
    const __half* Ab = A  + (size_t)m0 * EMBD;
    const __half* Bb = Bt + (size_t)n0 * EMBD;

    float c[2][8][4];
#pragma unroll
    for (int mt = 0; mt < 2; mt++)
#pragma unroll
        for (int nt = 0; nt < 8; nt++)
#pragma unroll
            for (int e = 0; e < 4; e++) c[mt][nt][e] = 0.f;

    auto load_tile = [&](int t) {
        __half* as = SA + (t % 3) * 128 * GSH;
        __half* bs = SB + (t % 3) * 128 * GSH;
        int kt = t * 64;
#pragma unroll
        for (int i = 0; i < 4; i++) {
            int idx = tid + i * 256;
            int r = idx >> 3, ch = idx & 7;
            cp16(as + r * GSH + ch * 8, Ab + (size_t)r * EMBD + kt + ch * 8);
        }
#pragma unroll
        for (int i = 0; i < 4; i++) {
            int idx = tid + i * 256;
            int r = idx >> 3, ch = idx & 7;
            cp16(bs + r * GSH + ch * 8, Bb + (size_t)r * EMBD + kt + ch * 8);
        }
    };

    load_tile(0); CP_COMMIT();
    load_tile(1); CP_COMMIT();

    const int a_row = (lane & 15), a_off = (lane >> 4) * 8;
    const int b_row = ((lane >> 4) & 1) * 8 + (lane & 7), b_off = ((lane >> 3) & 1) * 8;

    for (int t = 0; t < GKT; t++) {
        CP_WAIT(1);            // tile t resident (t+1 may be in flight)
        __syncthreads();       // all warps done iter t-1 (buf (t+2)%3 writable)
        if (t + 2 < GKT) { load_tile(t + 2); CP_COMMIT(); }
        else             { CP_COMMIT(); }
        uint32_t sa = smem_u32(SA + (t % 3) * 128 * GSH);
        uint32_t sb = smem_u32(SB + (t % 3) * 128 * GSH);

        uint32_t aA[2][4], aB[2][4];
        int kx0 = rev ? 48 : 0;            // first k16 step for this warp
#pragma unroll
        for (int mt = 0; mt < 2; mt++)
            ldm_x4(aA[mt], sa + 2 * ((wm * 32 + mt * 16 + a_row) * GSH + kx0 + a_off));
#pragma unroll
        for (int ks = 0; ks < 4; ks++) {
            int k0 = (rev ? (3 - ks) : ks) * 16;
            uint32_t b[4][4];
#pragma unroll
            for (int ng = 0; ng < 4; ng++)
                ldm_x4(b[ng], sb + 2 * ((wn * 64 + ng * 16 + b_row) * GSH + k0 + b_off));
            if (ks < 3) {
                int kn = (rev ? (2 - ks) : (ks + 1)) * 16;
#pragma unroll
                for (int mt = 0; mt < 2; mt++)
                    ldm_x4((ks & 1) ? aA[mt] : aB[mt],
                           sa + 2 * ((wm * 32 + mt * 16 + a_row) * GSH + kn + a_off));
            }
#pragma unroll
            for (int mt = 0; mt < 2; mt++) {
                const uint32_t* cur = (ks & 1) ? aB[mt] : aA[mt];
#pragma unroll
                for (int ng = 0; ng < 4; ng++) {
                    mma_f16(c[mt][2 * ng],     cur, b[ng]);
                    mma_f16(c[mt][2 * ng + 1], cur, b[ng] + 2);
                }
            }
        }
    }

    // epilogue: c0,c1 = row g cols 2t4,2t4+1; c2,c3 = row g+8
#pragma unroll
    for (int mt = 0; mt < 2; mt++) {
#pragma unroll
        for (int nt = 0; nt < 8; nt++) {
            int row0 = m0 + wm * 32 + mt * 16 + g;
            int row1 = row0 + 8;
            int col  = n0 + wn * 64 + nt * 8 + 2 * t4;
            float b0 = bias[col], b1 = bias[col + 1];
            float2 v0 = make_float2(c[mt][nt][0] + b0, c[mt][nt][1] + b1);
            float2 v1 = make_float2(c[mt][nt][2] + b0, c[mt][nt][3] + b1);
            if (mode == 0) {
                int sec = col >> 10, nn = col & 1023;
                int h = nn >> 6, d = nn & 63;
                int b_0 = row0 >> 11, s_0 = row0 & 2047;
                int b_1 = row1 >> 11, s_1 = row1 & 2047;
                size_t i0 = (((size_t)(b_0 * N_HEAD + h) * SEQ + s_0) << 6) + d;
                size_t i1 = (((size_t)(b_1 * N_HEAD + h) * SEQ + s_1) << 6) + d;
                if (sec == 0) {           // Q: fp16 scratch, pre-scaled for softmax
                    *(uint32_t*)&h0[i0] = packh2(v0.x * QSC, v0.y * QSC);
                    *(uint32_t*)&h0[i1] = packh2(v1.x * QSC, v1.y * QSC);
                } else if (sec == 1) {    // K: fp32 canonical + fp16 scratch
                    *(float2*)&o1[i0] = v0;
                    *(float2*)&o1[i1] = v1;
                    *(uint32_t*)&h1[i0] = packh2(v0.x, v0.y);
                    *(uint32_t*)&h1[i1] = packh2(v1.x, v1.y);
                } else {                  // V: fp32 canonical + fp16 scratch
                    *(float2*)&o2[i0] = v0;
                    *(float2*)&o2[i1] = v1;
                    *(uint32_t*)&h2[i0] = packh2(v0.x, v0.y);
                    *(uint32_t*)&h2[i1] = packh2(v1.x, v1.y);
                }
            } else {
                *(float2*)&o0[(size_t)row0 * EMBD + col] = v0;
                *(float2*)&o0[(size_t)row1 * EMBD + col] = v1;
            }
        }
    }
}

// ---------------- flash attention (fp16 mma, log2 softmax, MMA row-sum) ------
// Block: 128 queries x one (b,h); 8 warps, warp = 16 rows x 64 cols.
// 4x64-row KV ring, one barrier per TWO subtiles. Q fragments hoisted.
// Row-sum via ones-MMA; packed half2 max butterfly.
// Odd warps process each resident pair in REVERSE order (tp+1 then tp) so
// one warp's softmax chain overlaps another's S MMAs (online merge commutes).
#define FSH 72

__global__ __launch_bounds__(256, 2)
void flash_tc(const __half* __restrict__ q, const __half* __restrict__ k,
              const __half* __restrict__ v, __half* __restrict__ out)
{
    extern __shared__ __half smf[];
    __half* Qs = smf;                    // [128][FSH]
    __half* Ks = smf + 128 * FSH;        // [4][64][FSH]
    __half* Vs = Ks + 4 * 64 * FSH;      // [4][64][FSH]

    const int tid = threadIdx.x, wid = tid >> 5, lane = tid & 31;
    const int g = lane >> 2, t4 = lane & 3;
    const int qb = gridDim.x - 1 - blockIdx.x;   // big causal blocks first
    const int bh = blockIdx.y;
    const int q0 = qb * 128;
    const size_t base = (size_t)bh * SEQ * HEAD_DIM;
    const int qw = q0 + wid * 16;
    const int jtmax = 2 * qb + 1;                // odd: subtiles come in pairs

    auto load_kv = [&](int j) {
        __half* kd = Ks + (j & 3) * 64 * FSH;
        __half* vd = Vs + (j & 3) * 64 * FSH;
        const __half* kg = k + base + (size_t)j * 64 * 64;
        const __half* vg = v + base + (size_t)j * 64 * 64;
#pragma unroll
        for (int i = 0; i < 2; i++) {
            int idx = tid + i * 256;
            int r = idx >> 3, ch = idx & 7;
            cp16(kd + r * FSH + ch * 8, kg + (size_t)r * 64 + ch * 8);
            cp16(vd + r * FSH + ch * 8, vg + (size_t)r * 64 + ch * 8);
        }
    };

    // prologue: Q + first two KV subtiles, one group
#pragma unroll
    for (int i = 0; i < 4; i++) {
        int idx = tid + i * 256;
        int r = idx >> 3, ch = idx & 7;
        cp16(Qs + r * FSH + ch * 8, q + base + (size_t)(q0 + r) * 64 + ch * 8);
    }
    load_kv(0);
    load_kv(1);
    CP_COMMIT();

    float mr[2] = {-1e30f, -1e30f}, lr[2] = {0.f, 0.f};
    float o[8][4];
#pragma unroll
    for (int nt = 0; nt < 8; nt++)
#pragma unroll
        for (int e = 0; e < 4; e++) o[nt][e] = 0.f;

    const int a_row = (lane & 15), a_off = (lane >> 4) * 8;
    const int b_row = ((lane >> 4) & 1) * 8 + (lane & 7), b_off = ((lane >> 3) & 1) * 8;
    const int v_row = ((lane >> 3) & 1) * 8 + (lane & 7), v_off = (lane >> 4) * 8;

    uint32_t aq[4][4];   // hoisted Q fragments, one per k16 step
    const uint32_t onesb[2] = {0x3C003C00u, 0x3C003C00u};  // B-frag of 1.0h

    auto subtile = [&](int j) {
        if (j * 64 > qw + 15) return;        // fully masked for this warp
        uint32_t kb = smem_u32(Ks + (j & 3) * 64 * FSH);
        uint32_t vb = smem_u32(Vs + (j & 3) * 64 * FSH);

        // ---- S = Q K^T (already in log2 softmax domain) ----
        float s[8][4];
#pragma unroll
        for (int nt = 0; nt < 8; nt++)
#pragma unroll
            for (int e = 0; e < 4; e++) s[nt][e] = 0.f;
#pragma unroll
        for (int ks = 0; ks < 4; ks++) {
            int k0 = ks * 16;
            uint32_t bk[4][4];
#pragma unroll
            for (int ng = 0; ng < 4; ng++)
                ldm_x4(bk[ng], kb + 2 * ((ng * 16 + b_row) * FSH + k0 + b_off));
#pragma unroll
            for (int ng = 0; ng < 4; ng++) {
                mma_f16(s[2 * ng],     aq[ks], bk[ng]);
                mma_f16(s[2 * ng + 1], aq[ks], bk[ng] + 2);
            }
        }
        // ---- causal mask: only the diagonal subtile needs it ----
        if (j * 64 + 63 > qw) {
#pragma unroll
            for (int nt = 0; nt < 8; nt++) {
                int colb = j * 64 + nt * 8 + 2 * t4;
#pragma unroll
                for (int e = 0; e < 4; e++) {
                    int row = qw + g + (e >> 1) * 8;
                    int col = colb + (e & 1);
                    if (col > row) s[nt][e] = -1e30f;
                }
            }
        }
        // ---- row max: local fp32, butterfly packed in half2 (2 shfls) ----
        float mx0 = -1e30f, mx1 = -1e30f;
#pragma unroll
        for (int nt = 0; nt < 8; nt++) {
            mx0 = fmaxf(mx0, fmaxf(s[nt][0], s[nt][1]));
            mx1 = fmaxf(mx1, fmaxf(s[nt][2], s[nt][3]));
        }
        uint32_t mxp = packh2(mx0, mx1);
        {
            uint32_t u = __shfl_xor_sync(0xffffffffu, mxp, 1);
            __half2 hm = __hmax2(*(__half2*)&mxp, *(__half2*)&u);
            mxp = *(uint32_t*)&hm;
            u = __shfl_xor_sync(0xffffffffu, mxp, 2);
            hm = __hmax2(*(__half2*)&mxp, *(__half2*)&u);
            mxp = *(uint32_t*)&hm;
        }
        float2 mxf = __half22float2(*(__half2*)&mxp);
        float mn0 = fmaxf(mr[0], mxf.x), mn1 = fmaxf(mr[1], mxf.y);
        float al0 = ex2f(mr[0] - mn0), al1 = ex2f(mr[1] - mn1);
        mr[0] = mn0; mr[1] = mn1;
        // ---- p = ex2(s - mn) ----
#pragma unroll
        for (int nt = 0; nt < 8; nt++) {
            s[nt][0] = ex2f(s[nt][0] - mn0);
            s[nt][1] = ex2f(s[nt][1] - mn0);
            s[nt][2] = ex2f(s[nt][2] - mn1);
            s[nt][3] = ex2f(s[nt][3] - mn1);
        }
#pragma unroll
        for (int nt = 0; nt < 8; nt++) {
            o[nt][0] *= al0; o[nt][1] *= al0;
            o[nt][2] *= al1; o[nt][3] *= al1;
        }
        // ---- O += P V ; l += P 1 (row-sum via tensor pipe, no shfl) ----
        float lacc[4] = {0.f, 0.f, 0.f, 0.f};
#pragma unroll
        for (int jj = 0; jj < 4; jj++) {
            uint32_t ap[4];
            ap[0] = packh2(s[2 * jj][0],     s[2 * jj][1]);
            ap[1] = packh2(s[2 * jj][2],     s[2 * jj][3]);
            ap[2] = packh2(s[2 * jj + 1][0], s[2 * jj + 1][1]);
            ap[3] = packh2(s[2 * jj + 1][2], s[2 * jj + 1][3]);
            mma_f16(lacc, ap, onesb);
#pragma unroll
            for (int np = 0; np < 4; np++) {
                uint32_t bv[4];
                ldm_x4_t(bv, vb + 2 * ((16 * jj + v_row) * FSH + np * 16 + v_off));
                mma_f16(o[2 * np],     ap, bv);
                mma_f16(o[2 * np + 1], ap, bv + 2);
            }
        }
        lr[0] = lr[0] * al0 + lacc[0];
        lr[1] = lr[1] * al1 + lacc[2];
    };

    for (int tp = 0; tp <= jtmax; tp += 2) {
        CP_WAIT(0);            // tiles tp, tp+1 resident
        __syncthreads();       // all warps done pair tp-2 -> stages (tp+2)&3,(tp+3)&3 free
        if (tp == 0) {         // Q resident now: hoist fragments
#pragma unroll
            for (int ks = 0; ks < 4; ks++)
                ldm_x4(aq[ks], smem_u32(Qs) + 2 * ((wid * 16 + a_row) * FSH + ks * 16 + a_off));
        }
        if (tp + 2 <= jtmax) load_kv(tp + 2);
        if (tp + 3 <= jtmax) load_kv(tp + 3);
        CP_COMMIT();
        // stagger phases: odd warps do (tp+1, tp), even warps (tp, tp+1)
        if (wid & 1) { subtile(tp + 1); subtile(tp); }
        else         { subtile(tp);     subtile(tp + 1); }
    }

    // ---- normalize + store fp16 (A operand of proj GEMM) ----
    int b_ = bh >> 4, h = bh & 15;
    float i0 = 1.f / lr[0], i1 = 1.f / lr[1];
#pragma unroll
    for (int nt = 0; nt < 8; nt++) {
        int d = h * 64 + nt * 8 + 2 * t4;
        int r0 = qw + g, r1 = qw + 8 + g;
        *(uint32_t*)&out[(size_t)(b_ * SEQ + r0) * EMBD + d] = packh2(o[nt][0] * i0, o[nt][1] * i0);
        *(uint32_t*)&out[(size_t)(b_ * SEQ + r1) * EMBD + d] = packh2(o[nt][2] * i1, o[nt][3] * i1);
    }
}

// ---------------------------------------------------------------------------
extern "C" void kernel_launch(void* const* d_in, const int* in_sizes, int n_in,
                              void* d_out, int out_size)
{
    const float* x      = (const float*)d_in[0];
    const float* qkv_w  = (const float*)d_in[1];
    const float* qkv_b  = (const float*)d_in[2];
    const float* proj_w = (const float*)d_in[3];
    const float* proj_b = (const float*)d_in[4];

    float* out  = (float*)d_out;
    float* outK = out  + (size_t)BATCH * SEQ * EMBD;
    float* outV = outK + (size_t)BATCH * SEQ * EMBD;

    __half *qh, *kh, *vh, *ah, *xh, *wqh, *wph;
    cudaGetSymbolAddress((void**)&qh,  g_qh);
    cudaGetSymbolAddress((void**)&kh,  g_kh);
    cudaGetSymbolAddress((void**)&vh,  g_vh);
    cudaGetSymbolAddress((void**)&ah,  g_ah);
    cudaGetSymbolAddress((void**)&xh,  g_xh);
    cudaGetSymbolAddress((void**)&wqh, g_wqkvh);
    cudaGetSymbolAddress((void**)&wph, g_wprojh);

    const int gemm_smem  = 3 * 2 * 128 * GSH * (int)sizeof(__half);           // 110592
    const int flash_smem = (128 * FSH + 8 * 64 * FSH) * (int)sizeof(__half);  // 92160
    cudaFuncSetAttribute(gemm_tc,
                         cudaFuncAttributeMaxDynamicSharedMemorySize, gemm_smem);
    cudaFuncSetAttribute(flash_tc,
                         cudaFuncAttributeMaxDynamicSharedMemorySize, flash_smem);

    // 0) prep: convert x to fp16; transpose both weight matrices (one launch)
    to_half_kernel<<<(M_TOTAL * EMBD / 8 + 255) / 256, 256>>>(x, xh, M_TOTAL * EMBD / 8);
    transpose_both_kernel<<<dim3(128, EMBD / 32), dim3(32, 8)>>>(qkv_w, proj_w, wqh, wph);

    // 1) QKV GEMM -> Q fp16 (pre-scaled); K,V fp32 canonical + fp16 scratch
    gemm_tc<<<dim3(3 * EMBD / 128, M_TOTAL / 128), 256, gemm_smem>>>(
        xh, wqh, qkv_b, 0, nullptr, outK, outV, qh, kh, vh);

    // 2) causal flash attention (fp16 tensor cores, staggered warp phases)
    flash_tc<<<dim3(SEQ / 128, BATCH * N_HEAD), 256, flash_smem>>>(
        qh, kh, vh, ah);

    // 3) output projection (fp16 in, fp32 out)
    gemm_tc<<<dim3(EMBD / 128, M_TOTAL / 128), 256, gemm_smem>>>(
        ah, wph, proj_b, 1, out, nullptr, nullptr, nullptr, nullptr, nullptr);
}

// round 16
// speedup vs baseline: 1.0084x; 1.0084x over previous
#include <cuda_runtime.h>
#include <cuda_fp16.h>
#include <math.h>
#include <stdint.h>

#define N_HEAD   16
#define HEAD_DIM 64
#define EMBD     1024
#define BATCH    2
#define SEQ      2048
#define M_TOTAL  (BATCH*SEQ)   // 4096

// Q is pre-scaled by 1/sqrt(64) * log2(e) so flash softmax runs in log2 domain.
#define QSC 0.1803368801111204f

// ---------------- scratch (device globals; no allocs allowed) ---------------
__device__ __half g_qh[(size_t)BATCH*N_HEAD*SEQ*HEAD_DIM];   // Q fp16 (pre-scaled)
__device__ __half g_kh[(size_t)BATCH*N_HEAD*SEQ*HEAD_DIM];   // K fp16 copy
__device__ __half g_vh[(size_t)BATCH*N_HEAD*SEQ*HEAD_DIM];   // V fp16 copy
__device__ __half g_ah[(size_t)M_TOTAL*EMBD];                // attn out fp16 [B*S,E]
__device__ __half g_xh[(size_t)M_TOTAL*EMBD];                // x fp16
__device__ __half g_wqkvh[(size_t)3*EMBD*EMBD];              // W_qkv^T fp16 [3072,1024]
__device__ __half g_wprojh[(size_t)EMBD*EMBD];               // W_proj^T fp16 [1024,1024]

// ---------------- helpers ---------------------------------------------------
__device__ __forceinline__ uint32_t smem_u32(const void* p) {
    uint32_t a;
    asm("{ .reg .u64 t; cvta.to.shared.u64 t, %1; cvt.u32.u64 %0, t; }" : "=r"(a) : "l"(p));
    return a;
}
__device__ __forceinline__ uint32_t packh2(float x, float y) {
    __half2 h = __floats2half2_rn(x, y);
    return *(uint32_t*)&h;
}
__device__ __forceinline__ float ex2f(float x) {
    float y;
    asm("ex2.approx.f32 %0, %1;" : "=f"(y) : "f"(x));
    return y;
}
__device__ __forceinline__ void mma_f16(float* c, const uint32_t* a, const uint32_t* b) {
    asm volatile("mma.sync.aligned.m16n8k16.row.col.f32.f16.f16.f32 "
        "{%0,%1,%2,%3}, {%4,%5,%6,%7}, {%8,%9}, {%0,%1,%2,%3};"
        : "+f"(c[0]), "+f"(c[1]), "+f"(c[2]), "+f"(c[3])
        : "r"(a[0]), "r"(a[1]), "r"(a[2]), "r"(a[3]), "r"(b[0]), "r"(b[1]));
}
__device__ __forceinline__ void ldm_x4(uint32_t* r, uint32_t addr) {
    asm volatile("ldmatrix.sync.aligned.m8n8.x4.shared.b16 {%0,%1,%2,%3}, [%4];"
        : "=r"(r[0]), "=r"(r[1]), "=r"(r[2]), "=r"(r[3]) : "r"(addr));
}
__device__ __forceinline__ void ldm_x4_t(uint32_t* r, uint32_t addr) {
    asm volatile("ldmatrix.sync.aligned.m8n8.x4.trans.shared.b16 {%0,%1,%2,%3}, [%4];"
        : "=r"(r[0]), "=r"(r[1]), "=r"(r[2]), "=r"(r[3]) : "r"(addr));
}
__device__ __forceinline__ void cp16(void* dst_smem, const void* src) {
    uint32_t d = smem_u32(dst_smem);
    asm volatile("cp.async.cg.shared.global [%0], [%1], 16;" :: "r"(d), "l"(src) : "memory");
}
#define CP_COMMIT() asm volatile("cp.async.commit_group;" ::: "memory")
#define CP_WAIT(n)  asm volatile("cp.async.wait_group %0;" :: "n"(n) : "memory")

// ---------------- prep kernels ----------------------------------------------
__global__ __launch_bounds__(256)
void to_half_kernel(const float* __restrict__ x, __half* __restrict__ y, int n8)
{
    int i = blockIdx.x * blockDim.x + threadIdx.x;
    if (i < n8) {
        float4 a = ((const float4*)x)[2 * i];
        float4 b = ((const float4*)x)[2 * i + 1];
        uint4 o;
        o.x = packh2(a.x, a.y); o.y = packh2(a.z, a.w);
        o.z = packh2(b.x, b.y); o.w = packh2(b.z, b.w);
        ((uint4*)y)[i] = o;
    }
}

// Merged transpose of both weight matrices: blocks 0..95 -> qkv, 96..127 -> proj
__global__ __launch_bounds__(256)
void transpose_both_kernel(const float* __restrict__ Wq, const float* __restrict__ Wp,
                           __half* __restrict__ WTq, __half* __restrict__ WTp)
{
    __shared__ float t[32][33];
    bool is_q = blockIdx.x < 96;
    const float* W  = is_q ? Wq  : Wp;
    __half* WT      = is_q ? WTq : WTp;
    int N           = is_q ? 3 * EMBD : EMBD;
    int n0 = (is_q ? blockIdx.x : blockIdx.x - 96) * 32;
    int k0 = blockIdx.y * 32;
    int tx = threadIdx.x, ty = threadIdx.y;
#pragma unroll
    for (int i = 0; i < 4; i++)
        t[ty + 8 * i][tx] = W[(size_t)(k0 + ty + 8 * i) * N + n0 + tx];
    __syncthreads();
#pragma unroll
    for (int i = 0; i < 4; i++)
        WT[(size_t)(n0 + ty + 8 * i) * EMBD + k0 + tx] = __float2half(t[tx][ty + 8 * i]);
}

// ---------------- fp16 mma.sync GEMM ----------------------------------------
// C[M,Ntot] = A[M,1024] @ Bt^T + bias.  Block 128x128, BK=64, 3-stage cp.async,
// one barrier per K-tile, A-fragments register double-buffered across k16 steps.
// Odd warps traverse the 4 k16 steps in REVERSE order to stagger LDSM/MMA
// bursts across warps (accumulation order per warp is commutative). [R12 WIN]
#define GSH 72       // stride (halves) = 144B: 64 data + 8 pad; ldmatrix conflict-free
#define GKT (EMBD/64)

__global__ __launch_bounds__(256, 2)
void gemm_tc(const __half* __restrict__ A, const __half* __restrict__ Bt,
             const float* __restrict__ bias, int mode,
             float* __restrict__ o0, float* __restrict__ o1, float* __restrict__ o2,
             __half* __restrict__ h0, __half* __restrict__ h1, __half* __restrict__ h2)
{
    extern __shared__ __half smg[];
    __half* SA = smg;                      // [3][128*GSH]
    __half* SB = smg + 3 * 128 * GSH;      // [3][128*GSH]

    const int tid = threadIdx.x, wid = tid >> 5, lane = tid & 31;
    const int g = lane >> 2, t4 = lane & 3;
    const int wm = wid >> 1, wn = wid & 1;
    const int rev = wid & 1;               // odd warps run k16 steps 3..0
    const int m0 = blockIdx.y * 128, n0 = blockIdx.x * 128;
    const __half* Ab = A  + (size_t)m0 * EMBD;
    const __half* Bb = Bt + (size_t)n0 * EMBD;

    float c[2][8][4];
#pragma unroll
    for (int mt = 0; mt < 2; mt++)
#pragma unroll
        for (int nt = 0; nt < 8; nt++)
#pragma unroll
            for (int e = 0; e < 4; e++) c[mt][nt][e] = 0.f;

    auto load_tile = [&](int t) {
        __half* as = SA + (t % 3) * 128 * GSH;
        __half* bs = SB + (t % 3) * 128 * GSH;
        int kt = t * 64;
#pragma unroll
        for (int i = 0; i < 4; i++) {
            int idx = tid + i * 256;
            int r = idx >> 3, ch = idx & 7;
            cp16(as + r * GSH + ch * 8, Ab + (size_t)r * EMBD + kt + ch * 8);
        }
#pragma unroll
        for (int i = 0; i < 4; i++) {
            int idx = tid + i * 256;
            int r = idx >> 3, ch = idx & 7;
            cp16(bs + r * GSH + ch * 8, Bb + (size_t)r * EMBD + kt + ch * 8);
        }
    };

    load_tile(0); CP_COMMIT();
    load_tile(1); CP_COMMIT();

    const int a_row = (lane & 15), a_off = (lane >> 4) * 8;
    const int b_row = ((lane >> 4) & 1) * 8 + (lane & 7), b_off = ((lane >> 3) & 1) * 8;

    for (int t = 0; t < GKT; t++) {
        CP_WAIT(1);            // tile t resident (t+1 may be in flight)
        __syncthreads();       // all warps done iter t-1 (buf (t+2)%3 writable)
        if (t + 2 < GKT) { load_tile(t + 2); CP_COMMIT(); }
        else             { CP_COMMIT(); }
        uint32_t sa = smem_u32(SA + (t % 3) * 128 * GSH);
        uint32_t sb = smem_u32(SB + (t % 3) * 128 * GSH);

        uint32_t aA[2][4], aB[2][4];
        int kx0 = rev ? 48 : 0;            // first k16 step for this warp
#pragma unroll
        for (int mt = 0; mt < 2; mt++)
            ldm_x4(aA[mt], sa + 2 * ((wm * 32 + mt * 16 + a_row) * GSH + kx0 + a_off));
#pragma unroll
        for (int ks = 0; ks < 4; ks++) {
            int k0 = (rev ? (3 - ks) : ks) * 16;
            uint32_t b[4][4];
#pragma unroll
            for (int ng = 0; ng < 4; ng++)
                ldm_x4(b[ng], sb + 2 * ((wn * 64 + ng * 16 + b_row) * GSH + k0 + b_off));
            if (ks < 3) {
                int kn = (rev ? (2 - ks) : (ks + 1)) * 16;
#pragma unroll
                for (int mt = 0; mt < 2; mt++)
                    ldm_x4((ks & 1) ? aA[mt] : aB[mt],
                           sa + 2 * ((wm * 32 + mt * 16 + a_row) * GSH + kn + a_off));
            }
#pragma unroll
            for (int mt = 0; mt < 2; mt++) {
                const uint32_t* cur = (ks & 1) ? aB[mt] : aA[mt];
#pragma unroll
                for (int ng = 0; ng < 4; ng++) {
                    mma_f16(c[mt][2 * ng],     cur, b[ng]);
                    mma_f16(c[mt][2 * ng + 1], cur, b[ng] + 2);
                }
            }
        }
    }

    // epilogue: c0,c1 = row g cols 2t4,2t4+1; c2,c3 = row g+8
#pragma unroll
    for (int mt = 0; mt < 2; mt++) {
#pragma unroll
        for (int nt = 0; nt < 8; nt++) {
            int row0 = m0 + wm * 32 + mt * 16 + g;
            int row1 = row0 + 8;
            int col  = n0 + wn * 64 + nt * 8 + 2 * t4;
            float b0 = bias[col], b1 = bias[col + 1];
            float2 v0 = make_float2(c[mt][nt][0] + b0, c[mt][nt][1] + b1);
            float2 v1 = make_float2(c[mt][nt][2] + b0, c[mt][nt][3] + b1);
            if (mode == 0) {
                int sec = col >> 10, nn = col & 1023;
                int h = nn >> 6, d = nn & 63;
                int b_0 = row0 >> 11, s_0 = row0 & 2047;
                int b_1 = row1 >> 11, s_1 = row1 & 2047;
                size_t i0 = (((size_t)(b_0 * N_HEAD + h) * SEQ + s_0) << 6) + d;
                size_t i1 = (((size_t)(b_1 * N_HEAD + h) * SEQ + s_1) << 6) + d;
                if (sec == 0) {           // Q: fp16 scratch, pre-scaled for softmax
                    *(uint32_t*)&h0[i0] = packh2(v0.x * QSC, v0.y * QSC);
                    *(uint32_t*)&h0[i1] = packh2(v1.x * QSC, v1.y * QSC);
                } else if (sec == 1) {    // K: fp32 canonical + fp16 scratch
                    *(float2*)&o1[i0] = v0;
                    *(float2*)&o1[i1] = v1;
                    *(uint32_t*)&h1[i0] = packh2(v0.x, v0.y);
                    *(uint32_t*)&h1[i1] = packh2(v1.x, v1.y);
                } else {                  // V: fp32 canonical + fp16 scratch
                    *(float2*)&o2[i0] = v0;
                    *(float2*)&o2[i1] = v1;
                    *(uint32_t*)&h2[i0] = packh2(v0.x, v0.y);
                    *(uint32_t*)&h2[i1] = packh2(v1.x, v1.y);
                }
            } else {
                *(float2*)&o0[(size_t)row0 * EMBD + col] = v0;
                *(float2*)&o0[(size_t)row1 * EMBD + col] = v1;
            }
        }
    }
}

// ---------------- flash attention (fp16 mma, log2 softmax, MMA row-sum) ------
// Block: 128 queries x one (b,h); 8 warps, warp = 16 rows x 64 cols.
// 4x64-row KV ring, one barrier per TWO subtiles. Q fragments hoisted.
// Row-sum via ones-MMA; packed half2 max butterfly. [exact R11 kernel]
#define FSH 72

__global__ __launch_bounds__(256, 2)
void flash_tc(const __half* __restrict__ q, const __half* __restrict__ k,
              const __half* __restrict__ v, __half* __restrict__ out)
{
    extern __shared__ __half smf[];
    __half* Qs = smf;                    // [128][FSH]
    __half* Ks = smf + 128 * FSH;        // [4][64][FSH]
    __half* Vs = Ks + 4 * 64 * FSH;      // [4][64][FSH]

    const int tid = threadIdx.x, wid = tid >> 5, lane = tid & 31;
    const int g = lane >> 2, t4 = lane & 3;
    const int qb = gridDim.x - 1 - blockIdx.x;   // big causal blocks first
    const int bh = blockIdx.y;
    const int q0 = qb * 128;
    const size_t base = (size_t)bh * SEQ * HEAD_DIM;
    const int qw = q0 + wid * 16;
    const int jtmax = 2 * qb + 1;                // odd: subtiles come in pairs

    auto load_kv = [&](int j) {
        __half* kd = Ks + (j & 3) * 64 * FSH;
        __half* vd = Vs + (j & 3) * 64 * FSH;
        const __half* kg = k + base + (size_t)j * 64 * 64;
        const __half* vg = v + base + (size_t)j * 64 * 64;
#pragma unroll
        for (int i = 0; i < 2; i++) {
            int idx = tid + i * 256;
            int r = idx >> 3, ch = idx & 7;
            cp16(kd + r * FSH + ch * 8, kg + (size_t)r * 64 + ch * 8);
            cp16(vd + r * FSH + ch * 8, vg + (size_t)r * 64 + ch * 8);
        }
    };

    // prologue: Q + first two KV subtiles, one group
#pragma unroll
    for (int i = 0; i < 4; i++) {
        int idx = tid + i * 256;
        int r = idx >> 3, ch = idx & 7;
        cp16(Qs + r * FSH + ch * 8, q + base + (size_t)(q0 + r) * 64 + ch * 8);
    }
    load_kv(0);
    load_kv(1);
    CP_COMMIT();

    float mr[2] = {-1e30f, -1e30f}, lr[2] = {0.f, 0.f};
    float o[8][4];
#pragma unroll
    for (int nt = 0; nt < 8; nt++)
#pragma unroll
        for (int e = 0; e < 4; e++) o[nt][e] = 0.f;

    const int a_row = (lane & 15), a_off = (lane >> 4) * 8;
    const int b_row = ((lane >> 4) & 1) * 8 + (lane & 7), b_off = ((lane >> 3) & 1) * 8;
    const int v_row = ((lane >> 3) & 1) * 8 + (lane & 7), v_off = (lane >> 4) * 8;

    uint32_t aq[4][4];   // hoisted Q fragments, one per k16 step
    const uint32_t onesb[2] = {0x3C003C00u, 0x3C003C00u};  // B-frag of 1.0h

    auto subtile = [&](int j) {
        if (j * 64 > qw + 15) return;        // fully masked for this warp
        uint32_t kb = smem_u32(Ks + (j & 3) * 64 * FSH);
        uint32_t vb = smem_u32(Vs + (j & 3) * 64 * FSH);

        // ---- S = Q K^T (already in log2 softmax domain) ----
        float s[8][4];
#pragma unroll
        for (int nt = 0; nt < 8; nt++)
#pragma unroll
            for (int e = 0; e < 4; e++) s[nt][e] = 0.f;
#pragma unroll
        for (int ks = 0; ks < 4; ks++) {
            int k0 = ks * 16;
            uint32_t bk[4][4];
#pragma unroll
            for (int ng = 0; ng < 4; ng++)
                ldm_x4(bk[ng], kb + 2 * ((ng * 16 + b_row) * FSH + k0 + b_off));
#pragma unroll
            for (int ng = 0; ng < 4; ng++) {
                mma_f16(s[2 * ng],     aq[ks], bk[ng]);
                mma_f16(s[2 * ng + 1], aq[ks], bk[ng] + 2);
            }
        }
        // ---- causal mask: only the diagonal subtile needs it ----
        if (j * 64 + 63 > qw) {
#pragma unroll
            for (int nt = 0; nt < 8; nt++) {
                int colb = j * 64 + nt * 8 + 2 * t4;
#pragma unroll
                for (int e = 0; e < 4; e++) {
                    int row = qw + g + (e >> 1) * 8;
                    int col = colb + (e & 1);
                    if (col > row) s[nt][e] = -1e30f;
                }
            }
        }
        // ---- row max: local fp32, butterfly packed in half2 (2 shfls) ----
        float mx0 = -1e30f, mx1 = -1e30f;
#pragma unroll
        for (int nt = 0; nt < 8; nt++) {
            mx0 = fmaxf(mx0, fmaxf(s[nt][0], s[nt][1]));
            mx1 = fmaxf(mx1, fmaxf(s[nt][2], s[nt][3]));
        }
        uint32_t mxp = packh2(mx0, mx1);
        {
            uint32_t u = __shfl_xor_sync(0xffffffffu, mxp, 1);
            __half2 hm = __hmax2(*(__half2*)&mxp, *(__half2*)&u);
            mxp = *(uint32_t*)&hm;
            u = __shfl_xor_sync(0xffffffffu, mxp, 2);
            hm = __hmax2(*(__half2*)&mxp, *(__half2*)&u);
            mxp = *(uint32_t*)&hm;
        }
        float2 mxf = __half22float2(*(__half2*)&mxp);
        float mn0 = fmaxf(mr[0], mxf.x), mn1 = fmaxf(mr[1], mxf.y);
        float al0 = ex2f(mr[0] - mn0), al1 = ex2f(mr[1] - mn1);
        mr[0] = mn0; mr[1] = mn1;
        // ---- p = ex2(s - mn) ----
#pragma unroll
        for (int nt = 0; nt < 8; nt++) {
            s[nt][0] = ex2f(s[nt][0] - mn0);
            s[nt][1] = ex2f(s[nt][1] - mn0);
            s[nt][2] = ex2f(s[nt][2] - mn1);
            s[nt][3] = ex2f(s[nt][3] - mn1);
        }
#pragma unroll
        for (int nt = 0; nt < 8; nt++) {
            o[nt][0] *= al0; o[nt][1] *= al0;
            o[nt][2] *= al1; o[nt][3] *= al1;
        }
        // ---- O += P V ; l += P 1 (row-sum via tensor pipe, no shfl) ----
        float lacc[4] = {0.f, 0.f, 0.f, 0.f};
#pragma unroll
        for (int jj = 0; jj < 4; jj++) {
            uint32_t ap[4];
            ap[0] = packh2(s[2 * jj][0],     s[2 * jj][1]);
            ap[1] = packh2(s[2 * jj][2],     s[2 * jj][3]);
            ap[2] = packh2(s[2 * jj + 1][0], s[2 * jj + 1][1]);
            ap[3] = packh2(s[2 * jj + 1][2], s[2 * jj + 1][3]);
            mma_f16(lacc, ap, onesb);
#pragma unroll
            for (int np = 0; np < 4; np++) {
                uint32_t bv[4];
                ldm_x4_t(bv, vb + 2 * ((16 * jj + v_row) * FSH + np * 16 + v_off));
                mma_f16(o[2 * np],     ap, bv);
                mma_f16(o[2 * np + 1], ap, bv + 2);
            }
        }
        lr[0] = lr[0] * al0 + lacc[0];
        lr[1] = lr[1] * al1 + lacc[2];
    };

    for (int tp = 0; tp <= jtmax; tp += 2) {
        CP_WAIT(0);            // tiles tp, tp+1 resident
        __syncthreads();       // all warps done pair tp-2 -> stages (tp+2)&3,(tp+3)&3 free
        if (tp == 0) {         // Q resident now: hoist fragments
#pragma unroll
            for (int ks = 0; ks < 4; ks++)
                ldm_x4(aq[ks], smem_u32(Qs) + 2 * ((wid * 16 + a_row) * FSH + ks * 16 + a_off));
        }
        if (tp + 2 <= jtmax) load_kv(tp + 2);
        if (tp + 3 <= jtmax) load_kv(tp + 3);
        CP_COMMIT();
        subtile(tp);
        subtile(tp + 1);
    }

    // ---- normalize + store fp16 (A operand of proj GEMM) ----
    int b_ = bh >> 4, h = bh & 15;
    float i0 = 1.f / lr[0], i1 = 1.f / lr[1];
#pragma unroll
    for (int nt = 0; nt < 8; nt++) {
        int d = h * 64 + nt * 8 + 2 * t4;
        int r0 = qw + g, r1 = qw + 8 + g;
        *(uint32_t*)&out[(size_t)(b_ * SEQ + r0) * EMBD + d] = packh2(o[nt][0] * i0, o[nt][1] * i0);
        *(uint32_t*)&out[(size_t)(b_ * SEQ + r1) * EMBD + d] = packh2(o[nt][2] * i1, o[nt][3] * i1);
    }
}

// ---------------------------------------------------------------------------
extern "C" void kernel_launch(void* const* d_in, const int* in_sizes, int n_in,
                              void* d_out, int out_size)
{
    const float* x      = (const float*)d_in[0];
    const float* qkv_w  = (const float*)d_in[1];
    const float* qkv_b  = (const float*)d_in[2];
    const float* proj_w = (const float*)d_in[3];
    const float* proj_b = (const float*)d_in[4];

    float* out  = (float*)d_out;
    float* outK = out  + (size_t)BATCH * SEQ * EMBD;
    float* outV = outK + (size_t)BATCH * SEQ * EMBD;

    __half *qh, *kh, *vh, *ah, *xh, *wqh, *wph;
    cudaGetSymbolAddress((void**)&qh,  g_qh);
    cudaGetSymbolAddress((void**)&kh,  g_kh);
    cudaGetSymbolAddress((void**)&vh,  g_vh);
    cudaGetSymbolAddress((void**)&ah,  g_ah);
    cudaGetSymbolAddress((void**)&xh,  g_xh);
    cudaGetSymbolAddress((void**)&wqh, g_wqkvh);
    cudaGetSymbolAddress((void**)&wph, g_wprojh);

    const int gemm_smem  = 3 * 2 * 128 * GSH * (int)sizeof(__half);           // 110592
    const int flash_smem = (128 * FSH + 8 * 64 * FSH) * (int)sizeof(__half);  // 92160
    cudaFuncSetAttribute(gemm_tc,
                         cudaFuncAttributeMaxDynamicSharedMemorySize, gemm_smem);
    cudaFuncSetAttribute(flash_tc,
                         cudaFuncAttributeMaxDynamicSharedMemorySize, flash_smem);

    // 0) prep: convert x to fp16; transpose both weight matrices (one launch)
    to_half_kernel<<<(M_TOTAL * EMBD / 8 + 255) / 256, 256>>>(x, xh, M_TOTAL * EMBD / 8);
    transpose_both_kernel<<<dim3(128, EMBD / 32), dim3(32, 8)>>>(qkv_w, proj_w, wqh, wph);

    // 1) QKV GEMM -> Q fp16 (pre-scaled); K,V fp32 canonical + fp16 scratch
    gemm_tc<<<dim3(3 * EMBD / 128, M_TOTAL / 128), 256, gemm_smem>>>(
        xh, wqh, qkv_b, 0, nullptr, outK, outV, qh, kh, vh);

    // 2) causal flash attention (fp16 tensor cores, MMA row-sum softmax)
    flash_tc<<<dim3(SEQ / 128, BATCH * N_HEAD), 256, flash_smem>>>(
        qh, kh, vh, ah);

    // 3) output projection (fp16 in, fp32 out, staggered k16 warps)
    gemm_tc<<<dim3(EMBD / 128, M_TOTAL / 128), 256, gemm_smem>>>(
        ah, wph, proj_b, 1, out, nullptr, nullptr, nullptr, nullptr, nullptr);
}

// round 17
// speedup vs baseline: 1.0282x; 1.0196x over previous
#include <cuda_runtime.h>
#include <cuda_fp16.h>
#include <math.h>
#include <stdint.h>

#define N_HEAD   16
#define HEAD_DIM 64
#define EMBD     1024
#define BATCH    2
#define SEQ      2048
#define M_TOTAL  (BATCH*SEQ)   // 4096

// Q is pre-scaled by 1/sqrt(64) * log2(e) so flash softmax runs in log2 domain.
#define QSC 0.1803368801111204f

// ---------------- scratch (device globals; no allocs allowed) ---------------
__device__ __half g_qh[(size_t)BATCH*N_HEAD*SEQ*HEAD_DIM];   // Q fp16 (pre-scaled)
__device__ __half g_kh[(size_t)BATCH*N_HEAD*SEQ*HEAD_DIM];   // K fp16 copy
__device__ __half g_vh[(size_t)BATCH*N_HEAD*SEQ*HEAD_DIM];   // V fp16 copy
__device__ __half g_ah[(size_t)M_TOTAL*EMBD];                // attn out fp16 [B*S,E]
__device__ __half g_xh[(size_t)M_TOTAL*EMBD];                // x fp16
__device__ __half g_wqkvh[(size_t)3*EMBD*EMBD];              // W_qkv^T fp16 [3072,1024]
__device__ __half g_wprojh[(size_t)EMBD*EMBD];               // W_proj^T fp16 [1024,1024]

// ---------------- helpers ---------------------------------------------------
__device__ __forceinline__ uint32_t smem_u32(const void* p) {
    uint32_t a;
    asm("{ .reg .u64 t; cvta.to.shared.u64 t, %1; cvt.u32.u64 %0, t; }" : "=r"(a) : "l"(p));
    return a;
}
__device__ __forceinline__ uint32_t packh2(float x, float y) {
    __half2 h = __floats2half2_rn(x, y);
    return *(uint32_t*)&h;
}
__device__ __forceinline__ float ex2f(float x) {
    float y;
    asm("ex2.approx.f32 %0, %1;" : "=f"(y) : "f"(x));
    return y;
}
__device__ __forceinline__ void mma_f16(float* c, const uint32_t* a, const uint32_t* b) {
    asm volatile("mma.sync.aligned.m16n8k16.row.col.f32.f16.f16.f32 "
        "{%0,%1,%2,%3}, {%4,%5,%6,%7}, {%8,%9}, {%0,%1,%2,%3};"
        : "+f"(c[0]), "+f"(c[1]), "+f"(c[2]), "+f"(c[3])
        : "r"(a[0]), "r"(a[1]), "r"(a[2]), "r"(a[3]), "r"(b[0]), "r"(b[1]));
}
__device__ __forceinline__ void ldm_x4(uint32_t* r, uint32_t addr) {
    asm volatile("ldmatrix.sync.aligned.m8n8.x4.shared.b16 {%0,%1,%2,%3}, [%4];"
        : "=r"(r[0]), "=r"(r[1]), "=r"(r[2]), "=r"(r[3]) : "r"(addr));
}
__device__ __forceinline__ void ldm_x4_t(uint32_t* r, uint32_t addr) {
    asm volatile("ldmatrix.sync.aligned.m8n8.x4.trans.shared.b16 {%0,%1,%2,%3}, [%4];"
        : "=r"(r[0]), "=r"(r[1]), "=r"(r[2]), "=r"(r[3]) : "r"(addr));
}
__device__ __forceinline__ void cp16(void* dst_smem, const void* src) {
    uint32_t d = smem_u32(dst_smem);
    asm volatile("cp.async.cg.shared.global [%0], [%1], 16;" :: "r"(d), "l"(src) : "memory");
}
#define CP_COMMIT() asm volatile("cp.async.commit_group;" ::: "memory")
#define CP_WAIT(n)  asm volatile("cp.async.wait_group %0;" :: "n"(n) : "memory")

// ---------------- prep kernels ----------------------------------------------
__global__ __launch_bounds__(256)
void to_half_kernel(const float* __restrict__ x, __half* __restrict__ y, int n8)
{
    int i = blockIdx.x * blockDim.x + threadIdx.x;
    if (i < n8) {
        float4 a = ((const float4*)x)[2 * i];
        float4 b = ((const float4*)x)[2 * i + 1];
        uint4 o;
        o.x = packh2(a.x, a.y); o.y = packh2(a.z, a.w);
        o.z = packh2(b.x, b.y); o.w = packh2(b.z, b.w);
        ((uint4*)y)[i] = o;
    }
}

// Merged transpose of both weight matrices: blocks 0..95 -> qkv, 96..127 -> proj
__global__ __launch_bounds__(256)
void transpose_both_kernel(const float* __restrict__ Wq, const float* __restrict__ Wp,
                           __half* __restrict__ WTq, __half* __restrict__ WTp)
{
    __shared__ float t[32][33];
    bool is_q = blockIdx.x < 96;
    const float* W  = is_q ? Wq  : Wp;
    __half* WT      = is_q ? WTq : WTp;
    int N           = is_q ? 3 * EMBD : EMBD;
    int n0 = (is_q ? blockIdx.x : blockIdx.x - 96) * 32;
    int k0 = blockIdx.y * 32;
    int tx = threadIdx.x, ty = threadIdx.y;
#pragma unroll
    for (int i = 0; i < 4; i++)
        t[ty + 8 * i][tx] = W[(size_t)(k0 + ty + 8 * i) * N + n0 + tx];
    __syncthreads();
#pragma unroll
    for (int i = 0; i < 4; i++)
        WT[(size_t)(n0 + ty + 8 * i) * EMBD + k0 + tx] = __float2half(t[tx][ty + 8 * i]);
}

// ---------------- fp16 mma.sync GEMM ----------------------------------------
// C[M,Ntot] = A[M,1024] @ Bt^T + bias.  Block 128x128, BK=64, 3-stage cp.async,
// one barrier per K-tile, A-fragments register double-buffered across k16 steps.
// Odd warps traverse the 4 k16 steps in REVERSE order (R12 measured win).
#define GSH 72       // stride (halves) = 144B: 64 data + 8 pad; ldmatrix conflict-free
#define GKT (EMBD/64)

__global__ __launch_bounds__(256, 2)
void gemm_tc(const __half* __restrict__ A, const __half* __restrict__ Bt,
             const float* __restrict__ bias, int mode,
             float* __restrict__ o0, float* __restrict__ o1, float* __restrict__ o2,
             __half* __restrict__ h0, __half* __restrict__ h1, __half* __restrict__ h2)
{
    extern __shared__ __half smg[];
    __half* SA = smg;                      // [3][128*GSH]
    __half* SB = smg + 3 * 128 * GSH;      // [3][128*GSH]

    const int tid = threadIdx.x, wid = tid >> 5, lane = tid & 31;
    const int g = lane >> 2, t4 = lane & 3;
    const int wm = wid >> 1, wn = wid & 1;
    const int rev = wid & 1;               // odd warps run k16 steps 3..0
    const int m0 = blockIdx.y * 128, n0 = blockIdx.x * 128;
    const __half* Ab = A  + (size_t)m0 * EMBD;
    const __half* Bb = Bt + (size_t)n0 * EMBD;

    float c[2][8][4];
#pragma unroll
    for (int mt = 0; mt < 2; mt++)
#pragma unroll
        for (int nt = 0; nt < 8; nt++)
#pragma unroll
            for (int e = 0; e < 4; e++) c[mt][nt][e] = 0.f;

    auto load_tile = [&](int t) {
        __half* as = SA + (t % 3) * 128 * GSH;
        __half* bs = SB + (t % 3) * 128 * GSH;
        int kt = t * 64;
#pragma unroll
        for (int i = 0; i < 4; i++) {
            int idx = tid + i * 256;
            int r = idx >> 3, ch = idx & 7;
            cp16(as + r * GSH + ch * 8, Ab + (size_t)r * EMBD + kt + ch * 8);
        }
#pragma unroll
        for (int i = 0; i < 4; i++) {
            int idx = tid + i * 256;
            int r = idx >> 3, ch = idx & 7;
            cp16(bs + r * GSH + ch * 8, Bb + (size_t)r * EMBD + kt + ch * 8);
        }
    };

    load_tile(0); CP_COMMIT();
    load_tile(1); CP_COMMIT();

    const int a_row = (lane & 15), a_off = (lane >> 4) * 8;
    const int b_row = ((lane >> 4) & 1) * 8 + (lane & 7), b_off = ((lane >> 3) & 1) * 8;

    for (int t = 0; t < GKT; t++) {
        CP_WAIT(1);            // tile t resident (t+1 may be in flight)
        __syncthreads();       // all warps done iter t-1 (buf (t+2)%3 writable)
        if (t + 2 < GKT) { load_tile(t + 2); CP_COMMIT(); }
        else             { CP_COMMIT(); }
        uint32_t sa = smem_u32(SA + (t % 3) * 128 * GSH);
        uint32_t sb = smem_u32(SB + (t % 3) * 128 * GSH);

        uint32_t aA[2][4], aB[2][4];
        int kx0 = rev ? 48 : 0;            // first k16 step for this warp
#pragma unroll
        for (int mt = 0; mt < 2; mt++)
            ldm_x4(aA[mt], sa + 2 * ((wm * 32 + mt * 16 + a_row) * GSH + kx0 + a_off));
#pragma unroll
        for (int ks = 0; ks < 4; ks++) {
            int k0 = (rev ? (3 - ks) : ks) * 16;
            uint32_t b[4][4];
#pragma unroll
            for (int ng = 0; ng < 4; ng++)
                ldm_x4(b[ng], sb + 2 * ((wn * 64 + ng * 16 + b_row) * GSH + k0 + b_off));
            if (ks < 3) {
                int kn = (rev ? (2 - ks) : (ks + 1)) * 16;
#pragma unroll
                for (int mt = 0; mt < 2; mt++)
                    ldm_x4((ks & 1) ? aA[mt] : aB[mt],
                           sa + 2 * ((wm * 32 + mt * 16 + a_row) * GSH + kn + a_off));
            }
#pragma unroll
            for (int mt = 0; mt < 2; mt++) {
                const uint32_t* cur = (ks & 1) ? aB[mt] : aA[mt];
#pragma unroll
                for (int ng = 0; ng < 4; ng++) {
                    mma_f16(c[mt][2 * ng],     cur, b[ng]);
                    mma_f16(c[mt][2 * ng + 1], cur, b[ng] + 2);
                }
            }
        }
    }

    // epilogue: c0,c1 = row g cols 2t4,2t4+1; c2,c3 = row g+8
#pragma unroll
    for (int mt = 0; mt < 2; mt++) {
#pragma unroll
        for (int nt = 0; nt < 8; nt++) {
            int row0 = m0 + wm * 32 + mt * 16 + g;
            int row1 = row0 + 8;
            int col  = n0 + wn * 64 + nt * 8 + 2 * t4;
            float b0 = bias[col], b1 = bias[col + 1];
            float2 v0 = make_float2(c[mt][nt][0] + b0, c[mt][nt][1] + b1);
            float2 v1 = make_float2(c[mt][nt][2] + b0, c[mt][nt][3] + b1);
            if (mode == 0) {
                int sec = col >> 10, nn = col & 1023;
                int h = nn >> 6, d = nn & 63;
                int b_0 = row0 >> 11, s_0 = row0 & 2047;
                int b_1 = row1 >> 11, s_1 = row1 & 2047;
                size_t i0 = (((size_t)(b_0 * N_HEAD + h) * SEQ + s_0) << 6) + d;
                size_t i1 = (((size_t)(b_1 * N_HEAD + h) * SEQ + s_1) << 6) + d;
                if (sec == 0) {           // Q: fp16 scratch, pre-scaled for softmax
                    *(uint32_t*)&h0[i0] = packh2(v0.x * QSC, v0.y * QSC);
                    *(uint32_t*)&h0[i1] = packh2(v1.x * QSC, v1.y * QSC);
                } else if (sec == 1) {    // K: fp32 canonical + fp16 scratch
                    *(float2*)&o1[i0] = v0;
                    *(float2*)&o1[i1] = v1;
                    *(uint32_t*)&h1[i0] = packh2(v0.x, v0.y);
                    *(uint32_t*)&h1[i1] = packh2(v1.x, v1.y);
                } else {                  // V: fp32 canonical + fp16 scratch
                    *(float2*)&o2[i0] = v0;
                    *(float2*)&o2[i1] = v1;
                    *(uint32_t*)&h2[i0] = packh2(v0.x, v0.y);
                    *(uint32_t*)&h2[i1] = packh2(v1.x, v1.y);
                }
            } else {
                *(float2*)&o0[(size_t)row0 * EMBD + col] = v0;
                *(float2*)&o0[(size_t)row1 * EMBD + col] = v1;
            }
        }
    }
}

// ---------------- flash attention: 128-thread CTAs, 64-query tiles ----------
// 4 warps per CTA, warp = 16 rows x 64 cols; 4 CTAs/SM -> four independent
// pipelines per SM so one CTA's softmax overlaps another's MMAs.
// 2-stage KV ring (slot writes gated by top-of-loop barrier), log2 softmax,
// ones-MMA row-sum, packed half2 max butterfly, hoisted Q fragments.
#define FSH 72
#define FTHREADS 128

__global__ __launch_bounds__(FTHREADS, 4)
void flash_tc(const __half* __restrict__ q, const __half* __restrict__ k,
              const __half* __restrict__ v, __half* __restrict__ out)
{
    extern __shared__ __half smf[];
    __half* Qs = smf;                    // [64][FSH]
    __half* Ks = smf + 64 * FSH;         // [2][64][FSH]
    __half* Vs = Ks + 2 * 64 * FSH;      // [2][64][FSH]

    const int tid = threadIdx.x, wid = tid >> 5, lane = tid & 31;
    const int g = lane >> 2, t4 = lane & 3;
    const int qb = gridDim.x - 1 - blockIdx.x;   // big causal blocks first
    const int bh = blockIdx.y;
    const int q0 = qb * 64;
    const size_t base = (size_t)bh * SEQ * HEAD_DIM;
    const int qw = q0 + wid * 16;
    const int jtmax = qb;                        // keys up to q0+63

    auto load_kv = [&](int j) {
        __half* kd = Ks + (j & 1) * 64 * FSH;
        __half* vd = Vs + (j & 1) * 64 * FSH;
        const __half* kg = k + base + (size_t)j * 64 * 64;
        const __half* vg = v + base + (size_t)j * 64 * 64;
#pragma unroll
        for (int i = 0; i < 4; i++) {
            int idx = tid + i * FTHREADS;        // 512 chunks per operand
            int r = idx >> 3, ch = idx & 7;
            cp16(kd + r * FSH + ch * 8, kg + (size_t)r * 64 + ch * 8);
            cp16(vd + r * FSH + ch * 8, vg + (size_t)r * 64 + ch * 8);
        }
    };

    // prologue: Q tile + KV tile 0 in one group
#pragma unroll
    for (int i = 0; i < 4; i++) {
        int idx = tid + i * FTHREADS;            // 512 chunks
        int r = idx >> 3, ch = idx & 7;
        cp16(Qs + r * FSH + ch * 8, q + base + (size_t)(q0 + r) * 64 + ch * 8);
    }
    load_kv(0);
    CP_COMMIT();

    float mr[2] = {-1e30f, -1e30f}, lr[2] = {0.f, 0.f};
    float o[8][4];
#pragma unroll
    for (int nt = 0; nt < 8; nt++)
#pragma unroll
        for (int e = 0; e < 4; e++) o[nt][e] = 0.f;

    const int a_row = (lane & 15), a_off = (lane >> 4) * 8;
    const int b_row = ((lane >> 4) & 1) * 8 + (lane & 7), b_off = ((lane >> 3) & 1) * 8;
    const int v_row = ((lane >> 3) & 1) * 8 + (lane & 7), v_off = (lane >> 4) * 8;

    uint32_t aq[4][4];   // hoisted Q fragments, one per k16 step
    const uint32_t onesb[2] = {0x3C003C00u, 0x3C003C00u};  // B-frag of 1.0h

    for (int j = 0; j <= jtmax; j++) {
        __syncthreads();       // iter j-1 readers done -> slot (j+1)&1 writable
        if (j < jtmax) load_kv(j + 1);
        CP_COMMIT();           // one group per iteration (empty at j=jtmax)
        CP_WAIT(1);            // KV tile j (and Q at j=0) resident
        __syncthreads();       // cross-thread visibility of tile j
        if (j == 0) {          // Q resident: hoist fragments
#pragma unroll
            for (int ks = 0; ks < 4; ks++)
                ldm_x4(aq[ks], smem_u32(Qs) + 2 * ((wid * 16 + a_row) * FSH + ks * 16 + a_off));
        }
        if (j * 64 > qw + 15) continue;          // fully masked for this warp

        uint32_t kb = smem_u32(Ks + (j & 1) * 64 * FSH);
        uint32_t vb = smem_u32(Vs + (j & 1) * 64 * FSH);

        // ---- S = Q K^T (already in log2 softmax domain) ----
        float s[8][4];
#pragma unroll
        for (int nt = 0; nt < 8; nt++)
#pragma unroll
            for (int e = 0; e < 4; e++) s[nt][e] = 0.f;
#pragma unroll
        for (int ks = 0; ks < 4; ks++) {
            int k0 = ks * 16;
            uint32_t bk[4][4];
#pragma unroll
            for (int ng = 0; ng < 4; ng++)
                ldm_x4(bk[ng], kb + 2 * ((ng * 16 + b_row) * FSH + k0 + b_off));
#pragma unroll
            for (int ng = 0; ng < 4; ng++) {
                mma_f16(s[2 * ng],     aq[ks], bk[ng]);
                mma_f16(s[2 * ng + 1], aq[ks], bk[ng] + 2);
            }
        }
        // ---- causal mask: only the diagonal subtile needs it ----
        if (j * 64 + 63 > qw) {
#pragma unroll
            for (int nt = 0; nt < 8; nt++) {
                int colb = j * 64 + nt * 8 + 2 * t4;
#pragma unroll
                for (int e = 0; e < 4; e++) {
                    int row = qw + g + (e >> 1) * 8;
                    int col = colb + (e & 1);
                    if (col > row) s[nt][e] = -1e30f;
                }
            }
        }
        // ---- row max: local fp32, butterfly packed in half2 (2 shfls) ----
        float mx0 = -1e30f, mx1 = -1e30f;
#pragma unroll
        for (int nt = 0; nt < 8; nt++) {
            mx0 = fmaxf(mx0, fmaxf(s[nt][0], s[nt][1]));
            mx1 = fmaxf(mx1, fmaxf(s[nt][2], s[nt][3]));
        }
        uint32_t mxp = packh2(mx0, mx1);
        {
            uint32_t u = __shfl_xor_sync(0xffffffffu, mxp, 1);
            __half2 hm = __hmax2(*(__half2*)&mxp, *(__half2*)&u);
            mxp = *(uint32_t*)&hm;
            u = __shfl_xor_sync(0xffffffffu, mxp, 2);
            hm = __hmax2(*(__half2*)&mxp, *(__half2*)&u);
            mxp = *(uint32_t*)&hm;
        }
        float2 mxf = __half22float2(*(__half2*)&mxp);
        float mn0 = fmaxf(mr[0], mxf.x), mn1 = fmaxf(mr[1], mxf.y);
        float al0 = ex2f(mr[0] - mn0), al1 = ex2f(mr[1] - mn1);
        mr[0] = mn0; mr[1] = mn1;
        // ---- p = ex2(s - mn) ----
#pragma unroll
        for (int nt = 0; nt < 8; nt++) {
            s[nt][0] = ex2f(s[nt][0] - mn0);
            s[nt][1] = ex2f(s[nt][1] - mn0);
            s[nt][2] = ex2f(s[nt][2] - mn1);
            s[nt][3] = ex2f(s[nt][3] - mn1);
        }
#pragma unroll
        for (int nt = 0; nt < 8; nt++) {
            o[nt][0] *= al0; o[nt][1] *= al0;
            o[nt][2] *= al1; o[nt][3] *= al1;
        }
        // ---- O += P V ; l += P 1 (row-sum via tensor pipe, no shfl) ----
        float lacc[4] = {0.f, 0.f, 0.f, 0.f};
#pragma unroll
        for (int jj = 0; jj < 4; jj++) {
            uint32_t ap[4];
            ap[0] = packh2(s[2 * jj][0],     s[2 * jj][1]);
            ap[1] = packh2(s[2 * jj][2],     s[2 * jj][3]);
            ap[2] = packh2(s[2 * jj + 1][0], s[2 * jj + 1][1]);
            ap[3] = packh2(s[2 * jj + 1][2], s[2 * jj + 1][3]);
            mma_f16(lacc, ap, onesb);
#pragma unroll
            for (int np = 0; np < 4; np++) {
                uint32_t bv[4];
                ldm_x4_t(bv, vb + 2 * ((16 * jj + v_row) * FSH + np * 16 + v_off));
                mma_f16(o[2 * np],     ap, bv);
                mma_f16(o[2 * np + 1], ap, bv + 2);
            }
        }
        lr[0] = lr[0] * al0 + lacc[0];
        lr[1] = lr[1] * al1 + lacc[2];
    }

    // ---- normalize + store fp16 (A operand of proj GEMM) ----
    int b_ = bh >> 4, h = bh & 15;
    float i0 = 1.f / lr[0], i1 = 1.f / lr[1];
#pragma unroll
    for (int nt = 0; nt < 8; nt++) {
        int d = h * 64 + nt * 8 + 2 * t4;
        int r0 = qw + g, r1 = qw + 8 + g;
        *(uint32_t*)&out[(size_t)(b_ * SEQ + r0) * EMBD + d] = packh2(o[nt][0] * i0, o[nt][1] * i0);
        *(uint32_t*)&out[(size_t)(b_ * SEQ + r1) * EMBD + d] = packh2(o[nt][2] * i1, o[nt][3] * i1);
    }
}

// ---------------------------------------------------------------------------
extern "C" void kernel_launch(void* const* d_in, const int* in_sizes, int n_in,
                              void* d_out, int out_size)
{
    const float* x      = (const float*)d_in[0];
    const float* qkv_w  = (const float*)d_in[1];
    const float* qkv_b  = (const float*)d_in[2];
    const float* proj_w = (const float*)d_in[3];
    const float* proj_b = (const float*)d_in[4];

    float* out  = (float*)d_out;
    float* outK = out  + (size_t)BATCH * SEQ * EMBD;
    float* outV = outK + (size_t)BATCH * SEQ * EMBD;

    __half *qh, *kh, *vh, *ah, *xh, *wqh, *wph;
    cudaGetSymbolAddress((void**)&qh,  g_qh);
    cudaGetSymbolAddress((void**)&kh,  g_kh);
    cudaGetSymbolAddress((void**)&vh,  g_vh);
    cudaGetSymbolAddress((void**)&ah,  g_ah);
    cudaGetSymbolAddress((void**)&xh,  g_xh);
    cudaGetSymbolAddress((void**)&wqh, g_wqkvh);
    cudaGetSymbolAddress((void**)&wph, g_wprojh);

    const int gemm_smem  = 3 * 2 * 128 * GSH * (int)sizeof(__half);           // 110592
    const int flash_smem = (64 * FSH + 4 * 64 * FSH) * (int)sizeof(__half);   // 46080
    cudaFuncSetAttribute(gemm_tc,
                         cudaFuncAttributeMaxDynamicSharedMemorySize, gemm_smem);
    cudaFuncSetAttribute(flash_tc,
                         cudaFuncAttributeMaxDynamicSharedMemorySize, flash_smem);

    // 0) prep: convert x to fp16; transpose both weight matrices (one launch)
    to_half_kernel<<<(M_TOTAL * EMBD / 8 + 255) / 256, 256>>>(x, xh, M_TOTAL * EMBD / 8);
    transpose_both_kernel<<<dim3(128, EMBD / 32), dim3(32, 8)>>>(qkv_w, proj_w, wqh, wph);

    // 1) QKV GEMM -> Q fp16 (pre-scaled); K,V fp32 canonical + fp16 scratch
    gemm_tc<<<dim3(3 * EMBD / 128, M_TOTAL / 128), 256, gemm_smem>>>(
        xh, wqh, qkv_b, 0, nullptr, outK, outV, qh, kh, vh);

    // 2) causal flash attention: 128-thread CTAs, 64-query tiles, 4 CTAs/SM
    flash_tc<<<dim3(SEQ / 64, BATCH * N_HEAD), FTHREADS, flash_smem>>>(
        qh, kh, vh, ah);

    // 3) output projection (fp16 in, fp32 out, staggered k16 warps)
    gemm_tc<<<dim3(EMBD / 128, M_TOTAL / 128), 256, gemm_smem>>>(
        ah, wph, proj_b, 1, out, nullptr, nullptr, nullptr, nullptr, nullptr);
}